// round 11
// baseline (speedup 1.0000x reference)
#include <cuda_runtime.h>
#include <cstdint>
#include <cstddef>
#include <math_constants.h>

#define BB 4
#define NN 4096
#define CC 64
#define KK 16
#define KWPB 8           // warps per knn block (256 threads, 4 queries/warp)
#define QPW 4            // queries per warp
#define MW 8             // warps per mlp block
#define MT (MW*32)

// scratch (static device globals: no allocation allowed)
__device__ int g_knn[BB*NN*KK];

// ---- packed f32x2 helpers (FFMA2: only reachable via PTX fma.rn.f32x2) ----
__device__ __forceinline__ unsigned long long pack2(float lo, float hi){
  unsigned long long v;
  asm("mov.b64 %0, {%1,%2};" : "=l"(v) : "f"(lo), "f"(hi));
  return v;
}
__device__ __forceinline__ void unpack2(unsigned long long v, float &lo, float &hi){
  asm("mov.b64 {%0,%1}, %2;" : "=f"(lo), "=f"(hi) : "l"(v));
}
__device__ __forceinline__ unsigned long long ffma2(unsigned long long a,
                                                    unsigned long long b,
                                                    unsigned long long c){
  unsigned long long d;
  asm("fma.rn.f32x2 %0, %1, %2, %3;" : "=l"(d) : "l"(a), "l"(b), "l"(c));
  return d;
}
__device__ __forceinline__ unsigned long long relu2(unsigned long long v){
  float lo, hi; unpack2(v, lo, hi);
  return pack2(fmaxf(lo, 0.f), fmaxf(hi, 0.f));
}
__device__ __forceinline__ float qmax(ulonglong2 v){
  float a, b, c, d;
  unpack2(v.x, a, b); unpack2(v.y, c, d);
  return fmaxf(fmaxf(a, b), fmaxf(c, d));
}

// ============================================================================
// Kernel 1: two-pass warp-per-4-queries exact 16-NN (R9 logic, per-batch).
// ============================================================================
__device__ __forceinline__ void insert_hits(unsigned m, float d, int j0,
                                            float& myD, int& myI, float& worst,
                                            int lane){
  while (m){
    int src = __ffs(m) - 1; m &= m - 1;
    float cd = __shfl_sync(0xffffffffu, d, src);
    if (cd < worst){                                   // warp-uniform recheck
      unsigned em = __ballot_sync(0xffffffffu, (lane < KK) && (myD == worst));
      int leader = __ffs(em) - 1;
      if (lane == leader){ myD = cd; myI = j0 + src; }
      unsigned u = (lane < KK) ? __float_as_uint(myD) : 0u;
      worst = __uint_as_float(__reduce_max_sync(0xffffffffu, u));
    }
  }
}

__global__ __launch_bounds__(KWPB*32) void knn_warp(const float* __restrict__ xyz,
                                                    int b){
  extern __shared__ float4 s4[];               // 64KB: full point DB of one batch
  const float* base = xyz + (size_t)b * NN * 3;
  const int tid = threadIdx.x;
  for (int i = tid; i < NN; i += KWPB*32){
    float px = base[3*i], py = base[3*i+1], pz = base[3*i+2];
    s4[i] = make_float4(px, py, pz, fmaf(px, px, fmaf(py, py, pz*pz)));
  }
  __syncthreads();

  const int wid = tid >> 5, lane = tid & 31;
  const int qbase = (blockIdx.x * KWPB + wid) * QPW;
  const int qblk = qbase & ~31;                // 32-block containing all 4 q's

  float nx[QPW], ny[QPW], nz[QPW], qq[QPW];
  #pragma unroll
  for (int k = 0; k < QPW; k++){
    float4 qv = s4[qbase + k];
    nx[k] = -2.f*qv.x; ny[k] = -2.f*qv.y; nz[k] = -2.f*qv.z; qq[k] = qv.w;
  }

  // ---- pass A: per-lane minimum (self-contamination OK, handled by 17th) ----
  float lmin[QPW];
  #pragma unroll
  for (int k = 0; k < QPW; k++) lmin[k] = CUDART_INF_F;
  #pragma unroll 2
  for (int j0i = 0; j0i < NN; j0i += 32){
    float4 p = s4[j0i + lane];
    #pragma unroll
    for (int k = 0; k < QPW; k++){
      float d = fmaf(nx[k], p.x, fmaf(ny[k], p.y, fmaf(nz[k], p.z, qq[k] + p.w)));
      lmin[k] = fminf(lmin[k], d);
    }
  }

  // ---- tau: 17th smallest of 32 lane minima, then nextafter-up ----
  float tp[QPW];
  #pragma unroll
  for (int k = 0; k < QPW; k++){
    unsigned act = 0xffffffffu, mn = 0;
    const unsigned ub = __float_as_uint(lmin[k]);   // >= 0 -> uint order == float order
    for (int r = 0; r < 17; r++){
      unsigned u = ((act >> lane) & 1u) ? ub : 0x7f800000u;
      mn = __reduce_min_sync(0xffffffffu, u);
      unsigned eq = __ballot_sync(0xffffffffu, u == mn);
      act &= ~(1u << (__ffs(eq) - 1));
    }
    tp[k] = __uint_as_float(mn + 1u);               // strictly > tau >= D[15]
  }

  // ---- pass B: scan with tight sentinels ----
  float myD[QPW]; int myI[QPW]; float worst[QPW];
  #pragma unroll
  for (int k = 0; k < QPW; k++){ myD[k] = tp[k]; myI[k] = 0; worst[k] = tp[k]; }

  #pragma unroll 2
  for (int j0i = 0; j0i < NN; j0i += 32){
    float4 p = s4[j0i + lane];
    float d[QPW]; unsigned m[QPW];
    #pragma unroll
    for (int k = 0; k < QPW; k++){
      d[k] = fmaf(nx[k], p.x, fmaf(ny[k], p.y, fmaf(nz[k], p.z, qq[k] + p.w)));
      m[k] = __ballot_sync(0xffffffffu, d[k] < worst[k]);
    }
    if (j0i == qblk){                          // clear self bits (one iteration)
      #pragma unroll
      for (int k = 0; k < QPW; k++) m[k] &= ~(1u << ((qbase + k) - j0i));
    }
    #pragma unroll
    for (int k = 0; k < QPW; k++)
      if (m[k]) insert_hits(m[k], d[k], j0i, myD[k], myI[k], worst[k], lane);
  }

  if (lane < KK){
    #pragma unroll
    for (int k = 0; k < QPW; k++)
      g_knn[((size_t)b * NN + qbase + k) * KK + lane] = myI[k];
  }
}

// ============================================================================
// Kernel 2: m-tiled register GEMM MLP (exact R8 structure, per-batch).
// ============================================================================
__device__ __forceinline__ void gemm_layer(const float* __restrict__ wT,
                                           const float* __restrict__ h,
                                           int lane, ulonglong2* A, ulonglong2* B){
  #pragma unroll
  for (int c = 0; c < 8; c++){
    A[c].x = 0ull; A[c].y = 0ull; B[c].x = 0ull; B[c].y = 0ull;
  }
  #pragma unroll 2
  for (int j8 = 0; j8 < 8; j8++){
    #pragma unroll
    for (int jj = 0; jj < 8; jj++){
      const int j = j8*8 + jj;
      const int jx = j & 31;
      float wa0 = wT[j*64 + (lane ^ jx)];
      float wb0 = wT[j*64 + 32 + (lane ^ jx)];
      unsigned long long wa = pack2(wa0, wa0);
      unsigned long long wb = pack2(wb0, wb0);
      const ulonglong2* hrow = reinterpret_cast<const ulonglong2*>(h + j*32);
      #pragma unroll
      for (int c = 0; c < 8; c++){
        ulonglong2 hv = hrow[(c + jj) & 7];    // compile-time rotation
        A[c].x = ffma2(wa, hv.x, A[c].x);
        A[c].y = ffma2(wa, hv.y, A[c].y);
        B[c].x = ffma2(wb, hv.x, B[c].x);
        B[c].y = ffma2(wb, hv.y, B[c].y);
      }
    }
  }
}

__global__ __launch_bounds__(MT, 2) void mlp_kernel(
    const float* __restrict__ xyz,
    const float* __restrict__ w1,
    const float* __restrict__ w2,
    const float* __restrict__ w3,
    float* __restrict__ out,
    int b)
{
  extern __shared__ float sm[];
  float* w1s = sm;              // 256  (64 x (a,b,g,0))
  float* w2T = sm + 256;        // 4096 swizzled [c_in][c_out ^ (c_in&31)]
  float* w3T = w2T + 4096;      // 4096
  float* hb  = w3T + 4096;      // MW * 2048

  const int tid = threadIdx.x, wid = tid >> 5, lane = tid & 31;

  // -- hoisted gather: issue global loads before smem staging --
  const int n0 = blockIdx.x * (MW*2) + wid*2;    // local point pair in batch b
  const int mpt = lane >> 4;                      // which of the 2 points
  const int nb  = lane & 15;                      // neighbor id
  const int n = n0 + mpt;
  const float* xb = xyz + (size_t)b * NN * 3;

  const int ng = g_knn[((size_t)b * NN + n) * KK + nb];
  const float rx = xb[ng*3+0] - xb[n*3+0];
  const float ry = xb[ng*3+1] - xb[n*3+1];
  const float rz = xb[ng*3+2] - xb[n*3+2];

  for (int t = tid; t < 256; t += MT){
    int c = t >> 2, e = t & 3;
    w1s[t] = (e < 3) ? w1[c*3 + e] : 0.f;
  }
  for (int t = tid; t < 4096; t += MT){
    int o = t >> 6, c = t & 63;
    int phys = c*64 + (o ^ (c & 31));
    w2T[phys] = w2[t];
    w3T[phys] = w3[t];
  }
  __syncthreads();

  float* h = hb + wid * 2048;

  // ---- layer 1: h[c][m=lane] (rotated chunk layout), conflict-free stores ----
  {
    const int mc = lane >> 2, ml = lane & 3;
    const float4* w1v = reinterpret_cast<const float4*>(w1s);
    #pragma unroll 8
    for (int c = 0; c < CC; c++){
      float4 wv = w1v[c];
      float v = fmaxf(fmaf(wv.x, rx, fmaf(wv.y, ry, wv.z*rz)), 0.f);
      h[c*32 + (((mc + c) & 7) << 2) + ml] = v;
    }
  }
  __syncwarp();

  ulonglong2 A[8], Bacc[8];

  // ---- layer 2 ----
  gemm_layer(w2T, h, lane, A, Bacc);
  __syncwarp();                 // all reads of h done before overwrite
  #pragma unroll
  for (int c = 0; c < 8; c++){
    ulonglong2 va; va.x = relu2(A[c].x);    va.y = relu2(A[c].y);
    ulonglong2 vb; vb.x = relu2(Bacc[c].x); vb.y = relu2(Bacc[c].y);
    const int pc = ((c + lane) & 7) << 2;   // same rotation, rows lane / lane+32
    *reinterpret_cast<ulonglong2*>(h + lane*32 + pc)      = va;
    *reinterpret_cast<ulonglong2*>(h + (lane+32)*32 + pc) = vb;
  }
  __syncwarp();

  // ---- layer 3 + fused max-pool over neighbors ----
  gemm_layer(w3T, h, lane, A, Bacc);

  float a0 = -CUDART_INF_F, a1 = -CUDART_INF_F;   // o=lane:    ptA, ptB
  float b0 = -CUDART_INF_F, b1 = -CUDART_INF_F;   // o=lane+32: ptA, ptB
  #pragma unroll
  for (int c = 0; c < 4; c++){
    a0 = fmaxf(a0, qmax(A[c]));    b0 = fmaxf(b0, qmax(Bacc[c]));
    a1 = fmaxf(a1, qmax(A[c+4]));  b1 = fmaxf(b1, qmax(Bacc[c+4]));
  }
  out[((size_t)b*CC + lane)      * NN + n0]     = a0;
  out[((size_t)b*CC + lane)      * NN + n0 + 1] = a1;
  out[((size_t)b*CC + lane + 32) * NN + n0]     = b0;
  out[((size_t)b*CC + lane + 32) * NN + n0 + 1] = b1;
}

// ============================================================================
// Launch: per-batch pipeline. knn(b) runs on a side stream; mlp(b) on the
// main (capture) stream waits only on knn(b) via events -> knn(b+1) overlaps
// mlp(b). Fork/join pattern is stream-capture legal; identical semantics in
// the uncaptured correctness run.
// ============================================================================
extern "C" void kernel_launch(void* const* d_in, const int* in_sizes, int n_in,
                              void* d_out, int out_size)
{
  const float* xyz = (const float*)d_in[0];
  const float* w1  = (const float*)d_in[1];
  const float* w2  = (const float*)d_in[2];
  const float* w3  = (const float*)d_in[3];
  float* out = (float*)d_out;
  (void)in_sizes; (void)n_in; (void)out_size;

  static cudaStream_t ks = nullptr;
  static cudaEvent_t evFork = nullptr, evK[BB];
  if (ks == nullptr){
    cudaStreamCreateWithFlags(&ks, cudaStreamNonBlocking);
    cudaEventCreateWithFlags(&evFork, cudaEventDisableTiming);
    for (int b = 0; b < BB; b++)
      cudaEventCreateWithFlags(&evK[b], cudaEventDisableTiming);
  }

  size_t ksmem = (size_t)NN * sizeof(float4);   // 64KB
  cudaFuncSetAttribute(knn_warp, cudaFuncAttributeMaxDynamicSharedMemorySize, (int)ksmem);
  size_t msmem = (size_t)(256 + 4096 + 4096 + MW*2048) * sizeof(float); // 99328 B
  cudaFuncSetAttribute(mlp_kernel, cudaFuncAttributeMaxDynamicSharedMemorySize, (int)msmem);

  // fork side stream off the main stream
  cudaEventRecord(evFork, 0);
  cudaStreamWaitEvent(ks, evFork, 0);

  for (int b = 0; b < BB; b++){
    knn_warp<<<NN/(QPW*KWPB), KWPB*32, ksmem, ks>>>(xyz, b);
    cudaEventRecord(evK[b], ks);
  }
  for (int b = 0; b < BB; b++){
    cudaStreamWaitEvent(0, evK[b], 0);          // join: mlp(b) needs knn(b) only
    mlp_kernel<<<NN/(MW*2), MT, msmem, 0>>>(xyz, w1, w2, w3, out, b);
  }
}

// round 12
// speedup vs baseline: 1.4999x; 1.4999x over previous
#include <cuda_runtime.h>
#include <cstdint>
#include <cstddef>
#include <math_constants.h>

#define BB 4
#define NN 4096
#define CC 64
#define KK 16
#define KWPB 16          // warps per knn block (512 threads, 4 queries/warp)
#define QPW 4            // queries per warp
#define MW 8             // warps per mlp block
#define MT (MW*32)

// scratch (static device globals: no allocation allowed)
__device__ int g_knn[BB*NN*KK];

// ---- packed f32x2 helpers (FFMA2: only reachable via PTX fma.rn.f32x2) ----
__device__ __forceinline__ unsigned long long pack2(float lo, float hi){
  unsigned long long v;
  asm("mov.b64 %0, {%1,%2};" : "=l"(v) : "f"(lo), "f"(hi));
  return v;
}
__device__ __forceinline__ void unpack2(unsigned long long v, float &lo, float &hi){
  asm("mov.b64 {%0,%1}, %2;" : "=f"(lo), "=f"(hi) : "l"(v));
}
__device__ __forceinline__ unsigned long long ffma2(unsigned long long a,
                                                    unsigned long long b,
                                                    unsigned long long c){
  unsigned long long d;
  asm("fma.rn.f32x2 %0, %1, %2, %3;" : "=l"(d) : "l"(a), "l"(b), "l"(c));
  return d;
}
__device__ __forceinline__ unsigned long long relu2(unsigned long long v){
  float lo, hi; unpack2(v, lo, hi);
  return pack2(fmaxf(lo, 0.f), fmaxf(hi, 0.f));
}
__device__ __forceinline__ float qmax(ulonglong2 v){
  float a, b, c, d;
  unpack2(v.x, a, b); unpack2(v.y, c, d);
  return fmaxf(fmaxf(a, b), fmaxf(c, d));
}

// ============================================================================
// Kernel 1: two-pass warp-per-4-queries exact 16-NN.
// Pass A: branchless per-lane min over lane-striped points.
// tau    = 17th smallest of the 32 lane minima (bitonic sort, 15 shfl stages,
//          4 queries interleaved for ILP). Lane minima are distances to 32
//          DISTINCT points, so at most 15 non-self + self beat D[15] -> the
//          17th smallest lane-min >= D[15] (safe, tight threshold).
// Pass B: scan with sentinels = nextafter(tau): ~25 inserts/query.
// ============================================================================
__device__ __forceinline__ void insert_hits(unsigned m, float d, int j0,
                                            float& myD, int& myI, float& worst,
                                            int lane){
  while (m){
    int src = __ffs(m) - 1; m &= m - 1;
    float cd = __shfl_sync(0xffffffffu, d, src);
    if (cd < worst){                                   // warp-uniform recheck
      unsigned em = __ballot_sync(0xffffffffu, (lane < KK) && (myD == worst));
      int leader = __ffs(em) - 1;
      if (lane == leader){ myD = cd; myI = j0 + src; }
      unsigned u = (lane < KK) ? __float_as_uint(myD) : 0u;
      worst = __uint_as_float(__reduce_max_sync(0xffffffffu, u));
    }
  }
}

__global__ __launch_bounds__(KWPB*32) void knn_warp(const float* __restrict__ xyz){
  extern __shared__ float4 s4[];               // 64KB: full point DB of one batch
  const int b = blockIdx.y;
  const float* base = xyz + (size_t)b * NN * 3;
  const int tid = threadIdx.x;
  for (int i = tid; i < NN; i += KWPB*32){
    float px = base[3*i], py = base[3*i+1], pz = base[3*i+2];
    s4[i] = make_float4(px, py, pz, fmaf(px, px, fmaf(py, py, pz*pz)));
  }
  __syncthreads();

  const int wid = tid >> 5, lane = tid & 31;
  const int qbase = (blockIdx.x * KWPB + wid) * QPW;
  const int qblk = qbase & ~31;                // 32-block containing all 4 q's

  float nx[QPW], ny[QPW], nz[QPW], qq[QPW];
  #pragma unroll
  for (int k = 0; k < QPW; k++){
    float4 qv = s4[qbase + k];
    nx[k] = -2.f*qv.x; ny[k] = -2.f*qv.y; nz[k] = -2.f*qv.z; qq[k] = qv.w;
  }

  // ---- pass A: per-lane minimum (self-contamination OK, handled by 17th) ----
  float lmin[QPW];
  #pragma unroll
  for (int k = 0; k < QPW; k++) lmin[k] = CUDART_INF_F;
  #pragma unroll 2
  for (int j0i = 0; j0i < NN; j0i += 32){
    float4 p = s4[j0i + lane];
    #pragma unroll
    for (int k = 0; k < QPW; k++){
      float d = fmaf(nx[k], p.x, fmaf(ny[k], p.y, fmaf(nz[k], p.z, qq[k] + p.w)));
      lmin[k] = fminf(lmin[k], d);
    }
  }

  // ---- tau: bitonic sort the 32 lane minima, take rank 16, nextafter-up ----
  float tp[QPW];
  {
    float v[QPW];
    #pragma unroll
    for (int k = 0; k < QPW; k++) v[k] = lmin[k];
    #pragma unroll
    for (int sz = 2; sz <= 32; sz <<= 1){
      #pragma unroll
      for (int j = (sz >> 1); j > 0; j >>= 1){
        const bool up = ((lane & sz) == 0);
        const bool lower = ((lane & j) == 0);
        const bool takeMin = (lower == up);
        #pragma unroll
        for (int k = 0; k < QPW; k++){
          float o = __shfl_xor_sync(0xffffffffu, v[k], j);
          v[k] = takeMin ? fminf(v[k], o) : fmaxf(v[k], o);
        }
      }
    }
    #pragma unroll
    for (int k = 0; k < QPW; k++){
      float t16 = __shfl_sync(0xffffffffu, v[k], 16);   // 17th smallest
      tp[k] = __uint_as_float(__float_as_uint(t16) + 1u);
    }
  }

  // ---- pass B: scan with tight sentinels ----
  float myD[QPW]; int myI[QPW]; float worst[QPW];
  #pragma unroll
  for (int k = 0; k < QPW; k++){ myD[k] = tp[k]; myI[k] = 0; worst[k] = tp[k]; }

  #pragma unroll 2
  for (int j0i = 0; j0i < NN; j0i += 32){
    float4 p = s4[j0i + lane];
    float d[QPW]; unsigned m[QPW];
    #pragma unroll
    for (int k = 0; k < QPW; k++){
      d[k] = fmaf(nx[k], p.x, fmaf(ny[k], p.y, fmaf(nz[k], p.z, qq[k] + p.w)));
      m[k] = __ballot_sync(0xffffffffu, d[k] < worst[k]);
    }
    if (j0i == qblk){                          // clear self bits (one iteration)
      #pragma unroll
      for (int k = 0; k < QPW; k++) m[k] &= ~(1u << ((qbase + k) - j0i));
    }
    #pragma unroll
    for (int k = 0; k < QPW; k++)
      if (m[k]) insert_hits(m[k], d[k], j0i, myD[k], myI[k], worst[k], lane);
  }

  if (lane < KK){
    #pragma unroll
    for (int k = 0; k < QPW; k++)
      g_knn[((size_t)b * NN + qbase + k) * KK + lane] = myI[k];
  }
}

// ============================================================================
// Kernel 2: m-tiled register GEMM MLP (exact R8 structure).
// ============================================================================
__device__ __forceinline__ void gemm_layer(const float* __restrict__ wT,
                                           const float* __restrict__ h,
                                           int lane, ulonglong2* A, ulonglong2* B){
  #pragma unroll
  for (int c = 0; c < 8; c++){
    A[c].x = 0ull; A[c].y = 0ull; B[c].x = 0ull; B[c].y = 0ull;
  }
  #pragma unroll 2
  for (int j8 = 0; j8 < 8; j8++){
    #pragma unroll
    for (int jj = 0; jj < 8; jj++){
      const int j = j8*8 + jj;
      const int jx = j & 31;
      float wa0 = wT[j*64 + (lane ^ jx)];
      float wb0 = wT[j*64 + 32 + (lane ^ jx)];
      unsigned long long wa = pack2(wa0, wa0);
      unsigned long long wb = pack2(wb0, wb0);
      const ulonglong2* hrow = reinterpret_cast<const ulonglong2*>(h + j*32);
      #pragma unroll
      for (int c = 0; c < 8; c++){
        ulonglong2 hv = hrow[(c + jj) & 7];    // compile-time rotation
        A[c].x = ffma2(wa, hv.x, A[c].x);
        A[c].y = ffma2(wa, hv.y, A[c].y);
        B[c].x = ffma2(wb, hv.x, B[c].x);
        B[c].y = ffma2(wb, hv.y, B[c].y);
      }
    }
  }
}

__global__ __launch_bounds__(MT, 2) void mlp_kernel(
    const float* __restrict__ xyz,
    const float* __restrict__ w1,
    const float* __restrict__ w2,
    const float* __restrict__ w3,
    float* __restrict__ out)
{
  extern __shared__ float sm[];
  float* w1s = sm;              // 256  (64 x (a,b,g,0))
  float* w2T = sm + 256;        // 4096 swizzled [c_in][c_out ^ (c_in&31)]
  float* w3T = w2T + 4096;      // 4096
  float* hb  = w3T + 4096;      // MW * 2048

  const int tid = threadIdx.x, wid = tid >> 5, lane = tid & 31;

  // -- hoisted gather: issue global loads before smem staging --
  const int pt0 = blockIdx.x * (MW*2) + wid*2;   // 2 points per warp
  const int mpt = lane >> 4;                      // which of the 2 points
  const int nb  = lane & 15;                      // neighbor id
  const int point = pt0 + mpt;
  const int b = pt0 >> 12;                        // pair never straddles batch
  const int nA = pt0 & (NN-1), nB = nA + 1;
  const float* xb = xyz + (size_t)b * NN * 3;
  const int n = point & (NN-1);

  const int ng = g_knn[(size_t)point * KK + nb];
  const float rx = xb[ng*3+0] - xb[n*3+0];
  const float ry = xb[ng*3+1] - xb[n*3+1];
  const float rz = xb[ng*3+2] - xb[n*3+2];

  for (int t = tid; t < 256; t += MT){
    int c = t >> 2, e = t & 3;
    w1s[t] = (e < 3) ? w1[c*3 + e] : 0.f;
  }
  for (int t = tid; t < 4096; t += MT){
    int o = t >> 6, c = t & 63;
    int phys = c*64 + (o ^ (c & 31));
    w2T[phys] = w2[t];
    w3T[phys] = w3[t];
  }
  __syncthreads();

  float* h = hb + wid * 2048;

  // ---- layer 1: h[c][m=lane] (rotated chunk layout), conflict-free stores ----
  {
    const int mc = lane >> 2, ml = lane & 3;
    const float4* w1v = reinterpret_cast<const float4*>(w1s);
    #pragma unroll 8
    for (int c = 0; c < CC; c++){
      float4 wv = w1v[c];
      float v = fmaxf(fmaf(wv.x, rx, fmaf(wv.y, ry, wv.z*rz)), 0.f);
      h[c*32 + (((mc + c) & 7) << 2) + ml] = v;
    }
  }
  __syncwarp();

  ulonglong2 A[8], Bacc[8];

  // ---- layer 2 ----
  gemm_layer(w2T, h, lane, A, Bacc);
  __syncwarp();                 // all reads of h done before overwrite
  #pragma unroll
  for (int c = 0; c < 8; c++){
    ulonglong2 va; va.x = relu2(A[c].x);    va.y = relu2(A[c].y);
    ulonglong2 vb; vb.x = relu2(Bacc[c].x); vb.y = relu2(Bacc[c].y);
    const int pc = ((c + lane) & 7) << 2;   // same rotation, rows lane / lane+32
    *reinterpret_cast<ulonglong2*>(h + lane*32 + pc)      = va;
    *reinterpret_cast<ulonglong2*>(h + (lane+32)*32 + pc) = vb;
  }
  __syncwarp();

  // ---- layer 3 + fused max-pool over neighbors ----
  gemm_layer(w3T, h, lane, A, Bacc);

  float a0 = -CUDART_INF_F, a1 = -CUDART_INF_F;   // o=lane:    ptA, ptB
  float b0 = -CUDART_INF_F, b1 = -CUDART_INF_F;   // o=lane+32: ptA, ptB
  #pragma unroll
  for (int c = 0; c < 4; c++){
    a0 = fmaxf(a0, qmax(A[c]));    b0 = fmaxf(b0, qmax(Bacc[c]));
    a1 = fmaxf(a1, qmax(A[c+4]));  b1 = fmaxf(b1, qmax(Bacc[c+4]));
  }
  out[((size_t)b*CC + lane)      * NN + nA] = a0;
  out[((size_t)b*CC + lane)      * NN + nB] = a1;
  out[((size_t)b*CC + lane + 32) * NN + nA] = b0;
  out[((size_t)b*CC + lane + 32) * NN + nB] = b1;
}

// ============================================================================
extern "C" void kernel_launch(void* const* d_in, const int* in_sizes, int n_in,
                              void* d_out, int out_size)
{
  const float* xyz = (const float*)d_in[0];
  const float* w1  = (const float*)d_in[1];
  const float* w2  = (const float*)d_in[2];
  const float* w3  = (const float*)d_in[3];
  float* out = (float*)d_out;
  (void)in_sizes; (void)n_in; (void)out_size;

  size_t ksmem = (size_t)NN * sizeof(float4);   // 64KB
  cudaFuncSetAttribute(knn_warp, cudaFuncAttributeMaxDynamicSharedMemorySize, (int)ksmem);
  knn_warp<<<dim3(NN/(QPW*KWPB), BB), KWPB*32, ksmem>>>(xyz);

  size_t msmem = (size_t)(256 + 4096 + 4096 + MW*2048) * sizeof(float); // 99328 B
  cudaFuncSetAttribute(mlp_kernel, cudaFuncAttributeMaxDynamicSharedMemorySize, (int)msmem);
  mlp_kernel<<<(BB*NN)/(MW*2), MT, msmem>>>(xyz, w1, w2, w3, out);
}